// round 1
// baseline (speedup 1.0000x reference)
#include <cuda_runtime.h>
#include <math.h>
#include <stdint.h>

#define NN 30000
#define EE 480000
#define EN (EE + NN)
#define NF 128
#define SLOPE 0.02f

// ---------------- scratch (device globals; no allocation allowed) ----------
__device__ int   g_cnt[NN];
__device__ float g_dinv[NN];
__device__ int   g_rowptr[NN + 1];
__device__ int   g_fill[NN];
__device__ int   g_csr_src[EN];
__device__ float g_csr_w[EN];
__device__ float g_bufA[NN * NF];
__device__ float g_bufB[NN * NF];
__device__ int   g_is64;

// ---------------- edge-index dtype detection -------------------------------
__global__ void k_detect(const unsigned int* __restrict__ w) {
    // If edge_index is int64 (values < 2^31, non-negative), every odd 32-bit
    // word of the first 128 entries is 0. If int32, odd words are random edge
    // endpoints (all-zero has ~nil probability).
    int is64 = 1;
    for (int i = 0; i < 128; i++)
        if (w[2 * i + 1] != 0u) { is64 = 0; break; }
    g_is64 = is64;
}

__device__ __forceinline__ int edge_at(const void* ei, int idx) {
    return g_is64 ? (int)((const long long*)ei)[idx]
                  : ((const int*)ei)[idx];
}

// ---------------- graph preprocessing ---------------------------------------
__global__ void k_init_cnt() {
    int i = blockIdx.x * blockDim.x + threadIdx.x;
    if (i < NN) g_cnt[i] = 1;  // self-loop
}

__global__ void k_count(const void* __restrict__ ei) {
    int e = blockIdx.x * blockDim.x + threadIdx.x;
    if (e < EE) atomicAdd(&g_cnt[edge_at(ei, EE + e)], 1);
}

__global__ void k_dinv() {
    int i = blockIdx.x * blockDim.x + threadIdx.x;
    if (i < NN) g_dinv[i] = rsqrtf((float)g_cnt[i]);
}

__global__ void k_scan() {
    __shared__ int sh[1024];
    int tid = threadIdx.x;
    int off = 0;
    for (int base = 0; base < NN; base += 1024) {
        int i = base + tid;
        int v = (i < NN) ? g_cnt[i] : 0;
        sh[tid] = v;
        __syncthreads();
        #pragma unroll
        for (int d = 1; d < 1024; d <<= 1) {
            int add = (tid >= d) ? sh[tid - d] : 0;
            __syncthreads();
            sh[tid] += add;
            __syncthreads();
        }
        int incl = sh[tid];
        if (i < NN) {
            int excl = off + incl - v;
            g_rowptr[i] = excl;
            g_fill[i]   = excl;
        }
        off += sh[1023];
        __syncthreads();
    }
    if (tid == 0) g_rowptr[NN] = off;
}

__global__ void k_fill(const void* __restrict__ ei) {
    int e = blockIdx.x * blockDim.x + threadIdx.x;
    if (e < EE) {
        int s = edge_at(ei, e);
        int d = edge_at(ei, EE + e);
        int pos = atomicAdd(&g_fill[d], 1);
        g_csr_src[pos] = s;
        g_csr_w[pos]   = g_dinv[s] * g_dinv[d];
    } else if (e < EN) {
        int i = e - EE;
        int pos = atomicAdd(&g_fill[i], 1);
        float di = g_dinv[i];
        g_csr_src[pos] = i;
        g_csr_w[pos]   = di * di;
    }
}

// ---------------- aggregation kernels ---------------------------------------
// 64-dim: out[n,0:64] = sum_j w_j * x[src_j, 0:64]   (one warp per node)
__global__ void k_agg64(const float* __restrict__ X, float* __restrict__ out) {
    int n = (blockIdx.x * blockDim.x + threadIdx.x) >> 5;
    if (n >= NN) return;
    int lane = threadIdx.x & 31;
    int beg = g_rowptr[n], end = g_rowptr[n + 1];
    float2 acc = make_float2(0.f, 0.f);
    int j = beg;
    for (; j + 3 < end; j += 4) {
        int   s0 = g_csr_src[j],   s1 = g_csr_src[j+1],
              s2 = g_csr_src[j+2], s3 = g_csr_src[j+3];
        float w0 = g_csr_w[j],   w1 = g_csr_w[j+1],
              w2 = g_csr_w[j+2], w3 = g_csr_w[j+3];
        float2 v0 = __ldg((const float2*)(X + s0 * 64 + lane * 2));
        float2 v1 = __ldg((const float2*)(X + s1 * 64 + lane * 2));
        float2 v2 = __ldg((const float2*)(X + s2 * 64 + lane * 2));
        float2 v3 = __ldg((const float2*)(X + s3 * 64 + lane * 2));
        acc.x += w0*v0.x + w1*v1.x + w2*v2.x + w3*v3.x;
        acc.y += w0*v0.y + w1*v1.y + w2*v2.y + w3*v3.y;
    }
    for (; j < end; j++) {
        int s = g_csr_src[j]; float w = g_csr_w[j];
        float2 v = __ldg((const float2*)(X + s * 64 + lane * 2));
        acc.x += w * v.x; acc.y += w * v.y;
    }
    *(float2*)(out + n * 64 + lane * 2) = acc;
}

// 128-dim with bias epilogue (one warp per node, float4 per lane)
__global__ void k_agg128(const float* __restrict__ T, const float* __restrict__ bias,
                         float* __restrict__ out) {
    int n = (blockIdx.x * blockDim.x + threadIdx.x) >> 5;
    if (n >= NN) return;
    int lane = threadIdx.x & 31;
    int beg = g_rowptr[n], end = g_rowptr[n + 1];
    float4 acc = make_float4(0.f, 0.f, 0.f, 0.f);
    int j = beg;
    for (; j + 3 < end; j += 4) {
        int   s0 = g_csr_src[j],   s1 = g_csr_src[j+1],
              s2 = g_csr_src[j+2], s3 = g_csr_src[j+3];
        float w0 = g_csr_w[j],   w1 = g_csr_w[j+1],
              w2 = g_csr_w[j+2], w3 = g_csr_w[j+3];
        float4 v0 = __ldg((const float4*)(T + s0 * NF + lane * 4));
        float4 v1 = __ldg((const float4*)(T + s1 * NF + lane * 4));
        float4 v2 = __ldg((const float4*)(T + s2 * NF + lane * 4));
        float4 v3 = __ldg((const float4*)(T + s3 * NF + lane * 4));
        acc.x += w0*v0.x + w1*v1.x + w2*v2.x + w3*v3.x;
        acc.y += w0*v0.y + w1*v1.y + w2*v2.y + w3*v3.y;
        acc.z += w0*v0.z + w1*v1.z + w2*v2.z + w3*v3.z;
        acc.w += w0*v0.w + w1*v1.w + w2*v2.w + w3*v3.w;
    }
    for (; j < end; j++) {
        int s = g_csr_src[j]; float w = g_csr_w[j];
        float4 v = __ldg((const float4*)(T + s * NF + lane * 4));
        acc.x += w*v.x; acc.y += w*v.y; acc.z += w*v.z; acc.w += w*v.w;
    }
    float4 b = __ldg((const float4*)(bias + lane * 4));
    acc.x += b.x; acc.y += b.y; acc.z += b.z; acc.w += b.w;
    *(float4*)(out + n * NF + lane * 4) = acc;
}

// 3-dim final aggregation + bias + tanh*0.5
__global__ void k_agg3(const float* __restrict__ T, const float* __restrict__ bout,
                       float* __restrict__ out) {
    int n = (blockIdx.x * blockDim.x + threadIdx.x) >> 5;
    if (n >= NN) return;
    int lane = threadIdx.x & 31;
    int beg = g_rowptr[n], end = g_rowptr[n + 1];
    float a0 = 0.f, a1 = 0.f, a2 = 0.f;
    for (int j = beg + lane; j < end; j += 32) {
        int s = g_csr_src[j]; float w = g_csr_w[j];
        a0 += w * __ldg(T + s * 3 + 0);
        a1 += w * __ldg(T + s * 3 + 1);
        a2 += w * __ldg(T + s * 3 + 2);
    }
    #pragma unroll
    for (int o = 16; o > 0; o >>= 1) {
        a0 += __shfl_down_sync(0xffffffffu, a0, o);
        a1 += __shfl_down_sync(0xffffffffu, a1, o);
        a2 += __shfl_down_sync(0xffffffffu, a2, o);
    }
    if (lane == 0) {
        out[n * 3 + 0] = tanhf(a0 + __ldg(bout + 0)) * 0.5f;
        out[n * 3 + 1] = tanhf(a1 + __ldg(bout + 1)) * 0.5f;
        out[n * 3 + 2] = tanhf(a2 + __ldg(bout + 2)) * 0.5f;
    }
}

// ---------------- dense GEMM: out[N,128] = act(H[N,K]) @ W[K,128] (+ bias) --
// Tile: 32 nodes x 128 outs per 256-thread block; K chunked by 64.
template<int K, bool ACT, bool BIAS>
__global__ void __launch_bounds__(256) k_gemm(const float* __restrict__ H,
                                              const float* __restrict__ W,
                                              const float* __restrict__ bias,
                                              float* __restrict__ out) {
    __shared__ float sh_w[64][NF];   // 32 KB
    __shared__ float sh_h[32][64];   //  8 KB
    const int tid = threadIdx.x;
    const int node0 = blockIdx.x * 32;
    const int ng = (tid >> 5) * 4;   // node group within tile: 0..28
    const int fg = (tid & 31) * 4;   // output group: 0..124
    float acc[4][4] = {};

    for (int kc = 0; kc < K; kc += 64) {
        // W chunk: 64x128 floats = 2048 float4
        const float4* Wv = (const float4*)(W + kc * NF);
        #pragma unroll
        for (int i = 0; i < 8; i++)
            ((float4*)sh_w)[tid + i * 256] = Wv[tid + i * 256];
        // H chunk: 32 nodes x 64 k = 512 float4
        #pragma unroll
        for (int i = 0; i < 2; i++) {
            int idx = tid + i * 256;
            int nd = idx >> 4;          // 16 float4 per node row
            int kg = idx & 15;
            int node = node0 + nd;
            float4 v = make_float4(0.f, 0.f, 0.f, 0.f);
            if (node < NN)
                v = *(const float4*)(H + (size_t)node * K + kc + kg * 4);
            if (ACT) {
                v.x = v.x > 0.f ? v.x : v.x * SLOPE;
                v.y = v.y > 0.f ? v.y : v.y * SLOPE;
                v.z = v.z > 0.f ? v.z : v.z * SLOPE;
                v.w = v.w > 0.f ? v.w : v.w * SLOPE;
            }
            *(float4*)&sh_h[nd][kg * 4] = v;
        }
        __syncthreads();
        #pragma unroll
        for (int k = 0; k < 64; k++) {
            float4 wv = *(const float4*)&sh_w[k][fg];
            float h0 = sh_h[ng + 0][k];
            float h1 = sh_h[ng + 1][k];
            float h2 = sh_h[ng + 2][k];
            float h3 = sh_h[ng + 3][k];
            acc[0][0] += h0 * wv.x; acc[0][1] += h0 * wv.y;
            acc[0][2] += h0 * wv.z; acc[0][3] += h0 * wv.w;
            acc[1][0] += h1 * wv.x; acc[1][1] += h1 * wv.y;
            acc[1][2] += h1 * wv.z; acc[1][3] += h1 * wv.w;
            acc[2][0] += h2 * wv.x; acc[2][1] += h2 * wv.y;
            acc[2][2] += h2 * wv.z; acc[2][3] += h2 * wv.w;
            acc[3][0] += h3 * wv.x; acc[3][1] += h3 * wv.y;
            acc[3][2] += h3 * wv.z; acc[3][3] += h3 * wv.w;
        }
        __syncthreads();
    }

    float4 bv = make_float4(0.f, 0.f, 0.f, 0.f);
    if (BIAS) bv = *(const float4*)(bias + fg);
    #pragma unroll
    for (int i = 0; i < 4; i++) {
        int node = node0 + ng + i;
        if (node < NN) {
            float4 o;
            o.x = acc[i][0] + bv.x; o.y = acc[i][1] + bv.y;
            o.z = acc[i][2] + bv.z; o.w = acc[i][3] + bv.w;
            *(float4*)(out + (size_t)node * NF + fg) = o;
        }
    }
}

// out3[n,0:3] = leaky(H[n,:]) @ Wout[128,3]   (one warp per node)
__global__ void k_gemm3(const float* __restrict__ H, const float* __restrict__ W,
                        float* __restrict__ out) {
    int n = (blockIdx.x * blockDim.x + threadIdx.x) >> 5;
    if (n >= NN) return;
    int lane = threadIdx.x & 31;
    float4 h = *(const float4*)(H + n * NF + lane * 4);
    h.x = h.x > 0.f ? h.x : h.x * SLOPE;
    h.y = h.y > 0.f ? h.y : h.y * SLOPE;
    h.z = h.z > 0.f ? h.z : h.z * SLOPE;
    h.w = h.w > 0.f ? h.w : h.w * SLOPE;
    float hv[4] = {h.x, h.y, h.z, h.w};
    float a0 = 0.f, a1 = 0.f, a2 = 0.f;
    #pragma unroll
    for (int j = 0; j < 4; j++) {
        int k = lane * 4 + j;
        a0 += hv[j] * __ldg(W + k * 3 + 0);
        a1 += hv[j] * __ldg(W + k * 3 + 1);
        a2 += hv[j] * __ldg(W + k * 3 + 2);
    }
    #pragma unroll
    for (int o = 16; o > 0; o >>= 1) {
        a0 += __shfl_down_sync(0xffffffffu, a0, o);
        a1 += __shfl_down_sync(0xffffffffu, a1, o);
        a2 += __shfl_down_sync(0xffffffffu, a2, o);
    }
    if (lane == 0) {
        out[n * 3 + 0] = a0;
        out[n * 3 + 1] = a1;
        out[n * 3 + 2] = a2;
    }
}

// ---------------- launch -----------------------------------------------------
extern "C" void kernel_launch(void* const* d_in, const int* in_sizes, int n_in,
                              void* d_out, int out_size) {
    const float* x    = (const float*)d_in[0];
    const void*  ei   = d_in[1];
    const float* W0   = (const float*)d_in[2];
    const float* b0   = (const float*)d_in[3];
    const float* Wh   = (const float*)d_in[4];
    const float* bh   = (const float*)d_in[5];
    const float* Wout = (const float*)d_in[6];
    const float* bout = (const float*)d_in[7];
    float* out = (float*)d_out;

    void *pA, *pB;
    cudaGetSymbolAddress(&pA, g_bufA);
    cudaGetSymbolAddress(&pB, g_bufB);
    float* A = (float*)pA;
    float* B = (float*)pB;

    // graph preprocessing (runs every replay; cheap relative to layers)
    k_detect<<<1, 1>>>((const unsigned int*)ei);
    k_init_cnt<<<(NN + 255) / 256, 256>>>();
    k_count<<<(EE + 255) / 256, 256>>>(ei);
    k_dinv<<<(NN + 255) / 256, 256>>>();
    k_scan<<<1, 1024>>>();
    k_fill<<<(EN + 255) / 256, 256>>>(ei);

    const int warpBlocks = (NN * 32 + 255) / 256;   // one warp per node
    const int gemmBlocks = (NN + 31) / 32;

    // layer 0:  h = (A x) @ W0 + b0      (aggregate in 64-dim: A(xW)=(Ax)W)
    k_agg64<<<warpBlocks, 256>>>(x, A);
    k_gemm<64, false, true><<<gemmBlocks, 256>>>(A, W0, b0, B);

    // 6 hidden layers:  h = A(leaky(h) @ Wh[i]) + bh[i]
    for (int i = 0; i < 6; i++) {
        k_gemm<128, true, false><<<gemmBlocks, 256>>>(B, Wh + (size_t)i * NF * NF, nullptr, A);
        k_agg128<<<warpBlocks, 256>>>(A, bh + (size_t)i * NF, B);
    }

    // output layer: out = tanh(A(leaky(h) @ Wout) + bout) * 0.5
    //   (project to 3 dims BEFORE aggregating: 6 MB of gathers instead of 261 MB)
    k_gemm3<<<warpBlocks, 256>>>(B, Wout, A);
    k_agg3<<<warpBlocks, 256>>>(A, bout, out);
}